// round 8
// baseline (speedup 1.0000x reference)
#include <cuda_runtime.h>
#include <cstdint>

// Fixed problem shapes
#define NST   32      // categorical variables
#define SS    32      // classes per categorical
#define EE    128     // embedding size
#define ROWS  262144  // B*T*N

// libdevice accurate logf — the exact function XLA GPU lowers log.f32 to.
extern "C" __device__ float __nv_logf(float);

// Threefry-2x32, 20 rounds, key=(0,42), partitionable layout:
// counter=(hi=0, lo=i); bits = o0^o1.  (Confirmed bit-exact R2..R7.)
__device__ __forceinline__ uint32_t threefry_bits(uint32_t i) {
    const uint32_t k0 = 0u;
    const uint32_t k1 = 42u;
    const uint32_t k2 = 0u ^ 42u ^ 0x1BD11BDAu;
    uint32_t x0 = 0u + k0;
    uint32_t x1 = i + k1;
#define TF_RND(r) { x0 += x1; x1 = __funnelshift_l(x1, x1, (r)) ^ x0; }
    TF_RND(13) TF_RND(15) TF_RND(26) TF_RND(6)   x0 += k1; x1 += k2 + 1u;
    TF_RND(17) TF_RND(29) TF_RND(16) TF_RND(24)  x0 += k2; x1 += k0 + 2u;
    TF_RND(13) TF_RND(15) TF_RND(26) TF_RND(6)   x0 += k0; x1 += k1 + 3u;
    TF_RND(17) TF_RND(29) TF_RND(16) TF_RND(24)  x0 += k1; x1 += k2 + 4u;
    TF_RND(13) TF_RND(15) TF_RND(26) TF_RND(6)   x0 += k2; x1 += k0 + 5u;
#undef TF_RND
    return x0 ^ x1;
}

// bits -> jax uniform(FLT_MIN,1) -> gumbel, bit-exact vs XLA GPU.
// (float)(bits>>9) exact (<2^23); *2^-23 exact; equals |0x3F800000 - 1.0f
// by Sterbenz. I2F issues off the alu/fma pipes.
__device__ __forceinline__ float gumbel_from_bits(uint32_t bits) {
    float f = (float)(bits >> 9) * 1.1920928955078125e-7f;  // 2^-23
    float u = fmaxf(f, 1.17549435082228750797e-38f);        // FLT_MIN clamp
    return -__nv_logf(-__nv_logf(u));
}

// order-preserving float -> uint (monotone; equal floats -> equal keys)
__device__ __forceinline__ uint32_t float_ordered(float v) {
    uint32_t b = __float_as_uint(v);
    return b ^ (uint32_t)(((int32_t)b >> 31) | (int32_t)0x80000000);
}

#define RPW   8      // rows per warp per iteration
#define ITERS 4      // iterations per warp (1024 blocks x 8 warps x 32 rows)

__global__ void __launch_bounds__(256, 7)   // force regs<=36 -> 7 CTAs/SM -> 1 wave
categorical_encoder_kernel(const float* __restrict__ x,
                           const float* __restrict__ codebook,
                           float* __restrict__ out) {
    const int gwarp = (blockIdx.x * blockDim.x + threadIdx.x) >> 5;  // 0..8191
    const int lane  = threadIdx.x & 31;

#pragma unroll 1
    for (int it = 0; it < ITERS; it++) {
        // contiguous 8-row chunk; chunks strided so all warps stay hot
        const int rbase = (it * 8192 + gwarp) * RPW;
        const uint32_t ebase = ((uint32_t)rbase << 5) + (uint32_t)lane;

        // prefetch logits (8 independent LDGs)
        float lgt[RPW];
#pragma unroll
        for (int j = 0; j < RPW; j++)
            lgt[j] = __ldg(&x[ebase + (uint32_t)j * SS]);

        // 8 independent threefry chains
        uint32_t bits[RPW];
#pragma unroll
        for (int j = 0; j < RPW; j++)
            bits[j] = threefry_bits(ebase + (uint32_t)j * SS);

        float v[RPW];
#pragma unroll
        for (int j = 0; j < RPW; j++)
            v[j] = gumbel_from_bits(bits[j]) + lgt[j];

        // phase 1: all argmax indices
        int idx[RPW];
#pragma unroll
        for (int j = 0; j < RPW; j++) {
            const uint32_t u    = float_ordered(v[j]);
            const uint32_t umax = __reduce_max_sync(0xFFFFFFFFu, u);
            const uint32_t bal  = __ballot_sync(0xFFFFFFFFu, u == umax);
            idx[j] = __ffs(bal) - 1;   // first-index tiebreak (jnp.argmax)
        }

        // phase 2: all 8 codebook gathers in flight
        // rbase % 8 == 0, NST == 32 -> n = n0 + j, no wrap for j < 8
        const int n0 = rbase & (NST - 1);
        const float4* cb = reinterpret_cast<const float4*>(codebook)
                           + ((size_t)n0 * SS) * (EE / 4) + lane;
        float4 tmp[RPW];
#pragma unroll
        for (int j = 0; j < RPW; j++)
            tmp[j] = cb[(size_t)(j * SS + idx[j]) * (EE / 4)];

        // phase 3: all 8 stores
        float4* dst = reinterpret_cast<float4*>(out)
                      + (size_t)rbase * (EE / 4) + lane;
#pragma unroll
        for (int j = 0; j < RPW; j++)
            dst[(size_t)j * (EE / 4)] = tmp[j];
    }
}

extern "C" void kernel_launch(void* const* d_in, const int* in_sizes, int n_in,
                              void* d_out, int out_size) {
    const float* x        = (const float*)d_in[0];
    const float* codebook = (const float*)d_in[1];
    if (n_in >= 2 && in_sizes[0] < in_sizes[1]) {
        x        = (const float*)d_in[1];
        codebook = (const float*)d_in[0];
    }
    float* out = (float*)d_out;

    // single-wave persistent launch: 1024 CTAs (<= 148 SMs x 7 CTAs)
    categorical_encoder_kernel<<<1024, 256>>>(x, codebook, out);
}

// round 10
// speedup vs baseline: 1.0996x; 1.0996x over previous
#include <cuda_runtime.h>
#include <cstdint>

// Fixed problem shapes
#define NST  32      // categorical variables
#define SS   32      // classes per categorical
#define EE   128     // embedding size

// libdevice accurate logf — the exact function XLA GPU lowers log.f32 to.
extern "C" __device__ float __nv_logf(float);

// Threefry-2x32, 20 rounds, key=(0,42), partitionable layout:
// counter=(hi=0, lo=i); bits = o0^o1.  (Confirmed bit-exact R2..R8.)
__device__ __forceinline__ uint32_t threefry_bits(uint32_t i) {
    const uint32_t k0 = 0u;
    const uint32_t k1 = 42u;
    const uint32_t k2 = 0u ^ 42u ^ 0x1BD11BDAu;
    uint32_t x0 = 0u + k0;
    uint32_t x1 = i + k1;
#define TF_RND(r) { x0 += x1; x1 = __funnelshift_l(x1, x1, (r)) ^ x0; }
    TF_RND(13) TF_RND(15) TF_RND(26) TF_RND(6)   x0 += k1; x1 += k2 + 1u;
    TF_RND(17) TF_RND(29) TF_RND(16) TF_RND(24)  x0 += k2; x1 += k0 + 2u;
    TF_RND(13) TF_RND(15) TF_RND(26) TF_RND(6)   x0 += k0; x1 += k1 + 3u;
    TF_RND(17) TF_RND(29) TF_RND(16) TF_RND(24)  x0 += k1; x1 += k2 + 4u;
    TF_RND(13) TF_RND(15) TF_RND(26) TF_RND(6)   x0 += k2; x1 += k0 + 5u;
#undef TF_RND
    return x0 ^ x1;
}

// bits -> jax uniform(FLT_MIN,1) -> gumbel, bit-exact vs XLA GPU.
// (float)(bits>>9) exact (<2^23); *2^-23 exact; equals |0x3F800000 - 1.0f
// by Sterbenz. I2F issues off the alu/fma pipes.
__device__ __forceinline__ float gumbel_from_bits(uint32_t bits) {
    float f = (float)(bits >> 9) * 1.1920928955078125e-7f;  // 2^-23
    float u = fmaxf(f, 1.17549435082228750797e-38f);        // FLT_MIN clamp
    return -__nv_logf(-__nv_logf(u));
}

// order-preserving float -> uint (monotone; equal floats -> equal keys)
__device__ __forceinline__ uint32_t float_ordered(float v) {
    uint32_t b = __float_as_uint(v);
    return b ^ (uint32_t)(((int32_t)b >> 31) | (int32_t)0x80000000);
}

#define RPW 4   // rows per warp -> 65536 warps -> 6.92 waves @ 64 warps/SM (92% tail)

__global__ void __launch_bounds__(256)
categorical_encoder_kernel(const float* __restrict__ x,
                           const float* __restrict__ codebook,
                           float* __restrict__ out) {
    const int gwarp = (blockIdx.x * blockDim.x + threadIdx.x) >> 5;  // 0..65535
    const int lane  = threadIdx.x & 31;

    const int rbase = gwarp * RPW;
    const uint32_t ebase = ((uint32_t)rbase << 5) + (uint32_t)lane;

    // prefetch logits (4 independent LDGs)
    float lgt[RPW];
#pragma unroll
    for (int j = 0; j < RPW; j++)
        lgt[j] = __ldg(&x[ebase + (uint32_t)j * SS]);

    // 4 independent threefry chains
    uint32_t bits[RPW];
#pragma unroll
    for (int j = 0; j < RPW; j++)
        bits[j] = threefry_bits(ebase + (uint32_t)j * SS);

    float v[RPW];
#pragma unroll
    for (int j = 0; j < RPW; j++)
        v[j] = gumbel_from_bits(bits[j]) + lgt[j];

    // ---- phase 1: all argmax indices (batched REDUX/ballot) ----
    int idx[RPW];
#pragma unroll
    for (int j = 0; j < RPW; j++) {
        const uint32_t u    = float_ordered(v[j]);
        const uint32_t umax = __reduce_max_sync(0xFFFFFFFFu, u);
        const uint32_t bal  = __ballot_sync(0xFFFFFFFFu, u == umax);
        idx[j] = __ffs(bal) - 1;   // first-index tiebreak (jnp.argmax)
    }

    // ---- phase 2: all 4 codebook gathers in flight (one L2 round-trip) ----
    // rbase % 4 == 0, NST == 32 -> n = n0 + j with no wrap for j < 4
    const int n0 = rbase & (NST - 1);
    const float4* cb = reinterpret_cast<const float4*>(codebook)
                       + ((size_t)n0 * SS) * (EE / 4) + lane;
    float4 tmp[RPW];
#pragma unroll
    for (int j = 0; j < RPW; j++)
        tmp[j] = cb[(size_t)(j * SS + idx[j]) * (EE / 4)];

    // ---- phase 3: all 4 stores ----
    float4* dst = reinterpret_cast<float4*>(out) + (size_t)rbase * (EE / 4) + lane;
#pragma unroll
    for (int j = 0; j < RPW; j++)
        dst[(size_t)j * (EE / 4)] = tmp[j];
}

extern "C" void kernel_launch(void* const* d_in, const int* in_sizes, int n_in,
                              void* d_out, int out_size) {
    const float* x        = (const float*)d_in[0];
    const float* codebook = (const float*)d_in[1];
    if (n_in >= 2 && in_sizes[0] < in_sizes[1]) {
        x        = (const float*)d_in[1];
        codebook = (const float*)d_in[0];
    }
    float* out = (float*)d_out;

    // 262144 rows, 4 rows/warp, 8 warps/block -> 8192 blocks (65536 warps)
    categorical_encoder_kernel<<<8192, 256>>>(x, codebook, out);
}

// round 11
// speedup vs baseline: 1.2480x; 1.1350x over previous
#include <cuda_runtime.h>
#include <cstdint>

// Fixed problem shapes
#define NST  32      // categorical variables
#define SS   32      // classes per categorical
#define EE   128     // embedding size

// libdevice accurate logf — the exact function XLA GPU lowers log.f32 to.
extern "C" __device__ float __nv_logf(float);

// Threefry-2x32, 20 rounds, key=(0,42), partitionable layout:
// counter=(hi=0, lo=i); bits = o0^o1.  (Confirmed bit-exact R2..R10.)
__device__ __forceinline__ uint32_t threefry_bits(uint32_t i) {
    const uint32_t k0 = 0u;
    const uint32_t k1 = 42u;
    const uint32_t k2 = 0u ^ 42u ^ 0x1BD11BDAu;
    uint32_t x0 = 0u + k0;
    uint32_t x1 = i + k1;
#define TF_RND(r) { x0 += x1; x1 = __funnelshift_l(x1, x1, (r)) ^ x0; }
    TF_RND(13) TF_RND(15) TF_RND(26) TF_RND(6)   x0 += k1; x1 += k2 + 1u;
    TF_RND(17) TF_RND(29) TF_RND(16) TF_RND(24)  x0 += k2; x1 += k0 + 2u;
    TF_RND(13) TF_RND(15) TF_RND(26) TF_RND(6)   x0 += k0; x1 += k1 + 3u;
    TF_RND(17) TF_RND(29) TF_RND(16) TF_RND(24)  x0 += k1; x1 += k2 + 4u;
    TF_RND(13) TF_RND(15) TF_RND(26) TF_RND(6)   x0 += k2; x1 += k0 + 5u;
#undef TF_RND
    return x0 ^ x1;
}

// bits -> jax uniform(FLT_MIN,1); exact (I2F of <2^23 int, *2^-23, Sterbenz).
__device__ __forceinline__ float uniform_from_bits(uint32_t bits) {
    float f = (float)(bits >> 9) * 1.1920928955078125e-7f;  // 2^-23
    return fmaxf(f, 1.17549435082228750797e-38f);           // FLT_MIN clamp
}

// precise gumbel — bit-exact vs XLA GPU (used on slow path only)
__device__ __forceinline__ float gumbel_precise(uint32_t bits) {
    return -__nv_logf(-__nv_logf(uniform_from_bits(bits)));
}

// fast gumbel — MUFU.LG2 based, abs error <= ~1e-5 over the reachable range
__device__ __forceinline__ float gumbel_fast(uint32_t bits) {
    return -__logf(-__logf(uniform_from_bits(bits)));
}

// order-preserving float -> uint (monotone; equal floats -> equal keys)
__device__ __forceinline__ uint32_t float_ordered(float v) {
    uint32_t b = __float_as_uint(v);
    return b ^ (uint32_t)(((int32_t)b >> 31) | (int32_t)0x80000000);
}

// margin: fast-path winner must beat all others by E to be provably exact.
// true fast-log error bound ~1e-5 -> 100x safety. Slow-path rate ~1e-3/row.
#define E_MARGIN 1e-3f

#define RPW 4   // rows per warp

__global__ void __launch_bounds__(256)
categorical_encoder_kernel(const float* __restrict__ x,
                           const float* __restrict__ codebook,
                           float* __restrict__ out) {
    const int gwarp = (blockIdx.x * blockDim.x + threadIdx.x) >> 5;  // 0..65535
    const int lane  = threadIdx.x & 31;

    const int rbase = gwarp * RPW;
    const uint32_t ebase = ((uint32_t)rbase << 5) + (uint32_t)lane;

    // prefetch logits
    float lgt[RPW];
#pragma unroll
    for (int j = 0; j < RPW; j++)
        lgt[j] = __ldg(&x[ebase + (uint32_t)j * SS]);

    // 4 independent threefry chains
    uint32_t bits[RPW];
#pragma unroll
    for (int j = 0; j < RPW; j++)
        bits[j] = threefry_bits(ebase + (uint32_t)j * SS);

    // fast-path perturbed logits
    float v[RPW];
#pragma unroll
    for (int j = 0; j < RPW; j++)
        v[j] = gumbel_fast(bits[j]) + lgt[j];

    // ---- phase 1: argmax per row, speculative with exact fallback ----
    int idx[RPW];
#pragma unroll
    for (int j = 0; j < RPW; j++) {
        const uint32_t u    = float_ordered(v[j]);
        const uint32_t umax = __reduce_max_sync(0xFFFFFFFFu, u);
        const uint32_t bal  = __ballot_sync(0xFFFFFFFFu, u == umax);
        const int w = __ffs(bal) - 1;
        const float vmax = __shfl_sync(0xFFFFFFFFu, v[j], w);
        // certain iff every non-winner lane trails by more than the margin
        // (approx ties give vmax - v == 0 -> uncertain -> slow path)
        const bool safe = (vmax - v[j] > E_MARGIN) || (lane == w);
        if (__ballot_sync(0xFFFFFFFFu, safe) == 0xFFFFFFFFu) {
            idx[j] = w;
        } else {
            // slow path (~0.1% of rows): recompute bit-exact, full argmax
            const float vp = gumbel_precise(bits[j]) + lgt[j];
            const uint32_t up    = float_ordered(vp);
            const uint32_t upmax = __reduce_max_sync(0xFFFFFFFFu, up);
            const uint32_t pbal  = __ballot_sync(0xFFFFFFFFu, up == upmax);
            idx[j] = __ffs(pbal) - 1;   // first-index tiebreak (jnp.argmax)
        }
    }

    // ---- phase 2: all 4 codebook gathers in flight ----
    // rbase % 4 == 0, NST == 32 -> n = n0 + j with no wrap for j < 4
    const int n0 = rbase & (NST - 1);
    const float4* cb = reinterpret_cast<const float4*>(codebook)
                       + ((size_t)n0 * SS) * (EE / 4) + lane;
    float4 tmp[RPW];
#pragma unroll
    for (int j = 0; j < RPW; j++)
        tmp[j] = cb[(size_t)(j * SS + idx[j]) * (EE / 4)];

    // ---- phase 3: all 4 stores ----
    float4* dst = reinterpret_cast<float4*>(out) + (size_t)rbase * (EE / 4) + lane;
#pragma unroll
    for (int j = 0; j < RPW; j++)
        dst[(size_t)j * (EE / 4)] = tmp[j];
}

extern "C" void kernel_launch(void* const* d_in, const int* in_sizes, int n_in,
                              void* d_out, int out_size) {
    const float* x        = (const float*)d_in[0];
    const float* codebook = (const float*)d_in[1];
    if (n_in >= 2 && in_sizes[0] < in_sizes[1]) {
        x        = (const float*)d_in[1];
        codebook = (const float*)d_in[0];
    }
    float* out = (float*)d_out;

    // 262144 rows, 4 rows/warp, 8 warps/block -> 8192 blocks (65536 warps)
    categorical_encoder_kernel<<<8192, 256>>>(x, codebook, out);
}